// round 2
// baseline (speedup 1.0000x reference)
#include <cuda_runtime.h>
#include <math.h>

#define BM 128
#define BN 64
#define BK 32
#define XS_STRIDE (BM + 4)   // 132 floats
#define WS_STRIDE (BN + 4)   // 68 floats
#define LG_STRIDE (BN + 4)   // 68 floats
#define K_DIM 1024
#define N_EXPERTS 64

// smem: reused between (xs + ws) during GEMM and logits during epilogue.
// logits: 128*68 = 8704 floats = 34816 B (max of the two uses).
__global__ __launch_bounds__(128, 2)
void router_kernel(const float* __restrict__ x,
                   const float* __restrict__ W,
                   const float* __restrict__ bias,
                   float* __restrict__ out,
                   int num_tokens) {
    __shared__ float sbuf[BM * LG_STRIDE];
    float* xs = sbuf;                      // BK * XS_STRIDE = 4224 floats
    float* ws = sbuf + BK * XS_STRIDE;     // BK * WS_STRIDE = 2176 floats

    const int tid = threadIdx.x;
    const int txk = tid & 7;    // 8 k-groups (vector of 4 k each)
    const int tym = tid >> 3;   // 16 row-groups
    const int gm  = blockIdx.x * BM;

    float acc[8][8];
    #pragma unroll
    for (int i = 0; i < 8; ++i)
        #pragma unroll
        for (int j = 0; j < 8; ++j)
            acc[i][j] = 0.0f;

    for (int k0 = 0; k0 < K_DIM; k0 += BK) {
        __syncthreads();
        // ---- load x tile: [BK][BM] transposed, 128 rows x 32 k ----
        #pragma unroll
        for (int i = 0; i < 8; ++i) {
            const int m = tym + i * 16;
            const float4 v = *(const float4*)&x[(size_t)(gm + m) * K_DIM + k0 + txk * 4];
            xs[(txk * 4 + 0) * XS_STRIDE + m] = v.x;
            xs[(txk * 4 + 1) * XS_STRIDE + m] = v.y;
            xs[(txk * 4 + 2) * XS_STRIDE + m] = v.z;
            xs[(txk * 4 + 3) * XS_STRIDE + m] = v.w;
        }
        // ---- load W tile: [BK][BN] transposed, 64 rows x 32 k ----
        #pragma unroll
        for (int i = 0; i < 4; ++i) {
            const int n = tym + i * 16;
            const float4 v = *(const float4*)&W[(size_t)n * K_DIM + k0 + txk * 4];
            ws[(txk * 4 + 0) * WS_STRIDE + n] = v.x;
            ws[(txk * 4 + 1) * WS_STRIDE + n] = v.y;
            ws[(txk * 4 + 2) * WS_STRIDE + n] = v.z;
            ws[(txk * 4 + 3) * WS_STRIDE + n] = v.w;
        }
        __syncthreads();

        // ---- compute: each thread 8 tokens x 8 experts ----
        #pragma unroll 8
        for (int k = 0; k < BK; ++k) {
            const float4 a0 = *(const float4*)&xs[k * XS_STRIDE + tym * 8];
            const float4 a1 = *(const float4*)&xs[k * XS_STRIDE + tym * 8 + 4];
            const float4 b0 = *(const float4*)&ws[k * WS_STRIDE + txk * 8];
            const float4 b1 = *(const float4*)&ws[k * WS_STRIDE + txk * 8 + 4];
            const float am[8] = {a0.x, a0.y, a0.z, a0.w, a1.x, a1.y, a1.z, a1.w};
            const float bn[8] = {b0.x, b0.y, b0.z, b0.w, b1.x, b1.y, b1.z, b1.w};
            #pragma unroll
            for (int i = 0; i < 8; ++i)
                #pragma unroll
                for (int j = 0; j < 8; ++j)
                    acc[i][j] = fmaf(am[i], bn[j], acc[i][j]);
        }
    }

    // ---- dump logits to smem ----
    __syncthreads();
    #pragma unroll
    for (int i = 0; i < 8; ++i)
        #pragma unroll
        for (int j = 0; j < 8; ++j)
            sbuf[(tym * 8 + i) * LG_STRIDE + txk * 8 + j] = acc[i][j];
    __syncthreads();

    // ---- epilogue: one token per thread ----
    const float* lrow = &sbuf[tid * LG_STRIDE];

    float max1 = -INFINITY, max2 = -INFINITY;
    int i1 = 0, i2 = 0;
    #pragma unroll 8
    for (int e = 0; e < N_EXPERTS; ++e) {
        const float v = lrow[e] + bias[e];
        if (v > max1) { max2 = max1; i2 = i1; max1 = v; i1 = e; }
        else if (v > max2) { max2 = v; i2 = e; }
    }
    float s = 0.0f;
    #pragma unroll 8
    for (int e = 0; e < N_EXPERTS; ++e)
        s += expf(lrow[e] + bias[e] - max1);

    const float inv = 1.0f / s;
    const int token = gm + tid;
    // gates first, indices (as float) second
    out[token * 2 + 0] = inv;                         // exp(max1-max1)/s
    out[token * 2 + 1] = expf(max2 - max1) * inv;
    float* oid = out + (size_t)num_tokens * 2;
    oid[token * 2 + 0] = (float)i1;
    oid[token * 2 + 1] = (float)i2;
}

extern "C" void kernel_launch(void* const* d_in, const int* in_sizes, int n_in,
                              void* d_out, int out_size) {
    const float* x = (const float*)d_in[0];   // [8,4096,1024]
    const float* W = (const float*)d_in[1];   // [64,1024]
    const float* b = (const float*)d_in[2];   // [64]
    float* out = (float*)d_out;

    const int num_tokens = in_sizes[0] / K_DIM;   // 32768
    const int grid = num_tokens / BM;             // 256
    router_kernel<<<grid, 128>>>(x, W, b, out, num_tokens);
}

// round 3
// speedup vs baseline: 1.0160x; 1.0160x over previous
#include <cuda_runtime.h>
#include <math.h>

#define BM 128
#define BN 64
#define BK 32
#define XS_STRIDE (BM + 4)   // 132 floats
#define WS_STRIDE (BN + 4)   // 68 floats
#define K_DIM 1024
#define N_EXPERTS 64

typedef unsigned long long u64;

// one instruction, two fp32 FMAs (lanewise), fp32-exact per lane
__device__ __forceinline__ void ffma2(u64& d, u64 a, u64 b) {
    asm("fma.rn.f32x2 %0, %1, %2, %0;" : "+l"(d) : "l"(a), "l"(b));
}
__device__ __forceinline__ u64 bcast2(float v) {
    u64 r;
    asm("mov.b64 %0, {%1, %1};" : "=l"(r) : "f"(v));
    return r;
}
__device__ __forceinline__ float lo32(u64 u) { return __uint_as_float((unsigned)u); }
__device__ __forceinline__ float hi32(u64 u) { return __uint_as_float((unsigned)(u >> 32)); }

__global__ __launch_bounds__(128, 3)
void router_kernel(const float* __restrict__ x,
                   const float* __restrict__ W,
                   const float* __restrict__ bias,
                   float* __restrict__ out,
                   int num_tokens) {
    __shared__ float xs[BK * XS_STRIDE];   // 16896 B
    __shared__ float ws[BK * WS_STRIDE];   //  8704 B

    const int tid = threadIdx.x;
    const int txk = tid & 7;    // expert-group lane (8 experts each)
    const int tym = tid >> 3;   // token-group (8 tokens each)
    const int gm  = blockIdx.x * BM;

    // acc2[token][expert-pair]: low 32b = expert 2jp, high 32b = expert 2jp+1
    u64 acc2[8][4];
    #pragma unroll
    for (int i = 0; i < 8; ++i)
        #pragma unroll
        for (int jp = 0; jp < 4; ++jp)
            acc2[i][jp] = 0ULL;

    for (int k0 = 0; k0 < K_DIM; k0 += BK) {
        __syncthreads();
        // x tile: [BK][BM] transposed
        #pragma unroll
        for (int i = 0; i < 8; ++i) {
            const int m = tym + i * 16;
            const float4 v = *(const float4*)&x[(size_t)(gm + m) * K_DIM + k0 + txk * 4];
            xs[(txk * 4 + 0) * XS_STRIDE + m] = v.x;
            xs[(txk * 4 + 1) * XS_STRIDE + m] = v.y;
            xs[(txk * 4 + 2) * XS_STRIDE + m] = v.z;
            xs[(txk * 4 + 3) * XS_STRIDE + m] = v.w;
        }
        // W tile: [BK][BN] transposed
        #pragma unroll
        for (int i = 0; i < 4; ++i) {
            const int n = tym + i * 16;
            const float4 v = *(const float4*)&W[(size_t)n * K_DIM + k0 + txk * 4];
            ws[(txk * 4 + 0) * WS_STRIDE + n] = v.x;
            ws[(txk * 4 + 1) * WS_STRIDE + n] = v.y;
            ws[(txk * 4 + 2) * WS_STRIDE + n] = v.z;
            ws[(txk * 4 + 3) * WS_STRIDE + n] = v.w;
        }
        __syncthreads();

        #pragma unroll 4
        for (int k = 0; k < BK; ++k) {
            const float4 a0 = *(const float4*)&xs[k * XS_STRIDE + tym * 8];
            const float4 a1 = *(const float4*)&xs[k * XS_STRIDE + tym * 8 + 4];
            const ulonglong2 b0 = *(const ulonglong2*)&ws[k * WS_STRIDE + txk * 8];
            const ulonglong2 b1 = *(const ulonglong2*)&ws[k * WS_STRIDE + txk * 8 + 4];
            const u64 bp[4] = {b0.x, b0.y, b1.x, b1.y};
            const float am[8] = {a0.x, a0.y, a0.z, a0.w, a1.x, a1.y, a1.z, a1.w};
            #pragma unroll
            for (int i = 0; i < 8; ++i) {
                const u64 ab = bcast2(am[i]);
                #pragma unroll
                for (int jp = 0; jp < 4; ++jp)
                    ffma2(acc2[i][jp], ab, bp[jp]);
            }
        }
    }

    // ---- epilogue: per-token top-2 + softmax via shuffles over the 8 expert lanes ----
    // (lanes sharing tym are consecutive lanes txk=0..7 of the same warp)
    float bl[8];
    #pragma unroll
    for (int j = 0; j < 8; ++j)
        bl[j] = bias[txk * 8 + j];

    const int token_base = gm + tym * 8;
    float* oid = out + (size_t)num_tokens * 2;

    #pragma unroll
    for (int i = 0; i < 8; ++i) {
        float v[8];
        #pragma unroll
        for (int jp = 0; jp < 4; ++jp) {
            v[2 * jp + 0] = lo32(acc2[i][jp]) + bl[2 * jp + 0];
            v[2 * jp + 1] = hi32(acc2[i][jp]) + bl[2 * jp + 1];
        }
        // local top-2 over this thread's 8 experts
        float m1 = -INFINITY, m2 = -INFINITY;
        int i1 = 0, i2 = 0;
        #pragma unroll
        for (int j = 0; j < 8; ++j) {
            const int e = txk * 8 + j;
            if (v[j] > m1) { m2 = m1; i2 = i1; m1 = v[j]; i1 = e; }
            else if (v[j] > m2) { m2 = v[j]; i2 = e; }
        }
        // merge across 8 lanes
        #pragma unroll
        for (int d = 1; d < 8; d <<= 1) {
            const float om1 = __shfl_xor_sync(0xffffffffu, m1, d);
            const float om2 = __shfl_xor_sync(0xffffffffu, m2, d);
            const int   oi1 = __shfl_xor_sync(0xffffffffu, i1, d);
            const int   oi2 = __shfl_xor_sync(0xffffffffu, i2, d);
            if (om1 > m1) {
                if (m1 > om2) { m2 = m1; i2 = i1; }
                else          { m2 = om2; i2 = oi2; }
                m1 = om1; i1 = oi1;
            } else if (om1 > m2) {
                m2 = om1; i2 = oi1;
            }
        }
        // softmax denominator with global max
        float s = 0.0f;
        #pragma unroll
        for (int j = 0; j < 8; ++j)
            s += __expf(v[j] - m1);
        #pragma unroll
        for (int d = 1; d < 8; d <<= 1)
            s += __shfl_xor_sync(0xffffffffu, s, d);

        if (txk == 0) {
            const float inv = 1.0f / s;
            const int token = token_base + i;
            float2 g = make_float2(inv, __expf(m2 - m1) * inv);
            float2 id = make_float2((float)i1, (float)i2);
            *(float2*)&out[token * 2] = g;
            *(float2*)&oid[token * 2] = id;
        }
    }
}

extern "C" void kernel_launch(void* const* d_in, const int* in_sizes, int n_in,
                              void* d_out, int out_size) {
    const float* x = (const float*)d_in[0];   // [8,4096,1024]
    const float* W = (const float*)d_in[1];   // [64,1024]
    const float* b = (const float*)d_in[2];   // [64]
    float* out = (float*)d_out;

    const int num_tokens = in_sizes[0] / K_DIM;   // 32768
    const int grid = num_tokens / BM;             // 256
    router_kernel<<<grid, 128>>>(x, W, b, out, num_tokens);
}